// round 1
// baseline (speedup 1.0000x reference)
#include <cuda_runtime.h>

#define WID 512
#define NT  180

// grid: (2, NT) — blockIdx.x selects column half, blockIdx.y = theta
// block: 256 threads, one per output column c; each thread handles BOTH batches.
__global__ __launch_bounds__(256) void radon_kernel(
    const float* __restrict__ img,   // [2, 512, 512]
    float* __restrict__ out)         // [2, 512, 180] as (n, c, t)
{
    const int t = blockIdx.y;
    const int c = blockIdx.x * 256 + threadIdx.x;

    // theta = deg2rad(t) in fp32, matching jnp.deg2rad(arange(180, f32))
    const float th = (float)t * 0.017453292519943295f;
    float s, co;
    sincosf(th, &s, &co);

    const float u = (float)c - 255.5f;
    // ix(r) = co*u + s*(r - 255.5) + 255.5 ;  iy(r) = -s*u + co*(r - 255.5) + 255.5
    const float ix0 = fmaf(co, u, fmaf(s, -255.5f, 255.5f));
    const float iy0 = fmaf(-s, u, fmaf(co, -255.5f, 255.5f));

    const float* __restrict__ img0 = img;
    const float* __restrict__ img1 = img + WID * WID;

    float sum0 = 0.0f, sum1 = 0.0f;

#pragma unroll 4
    for (int r = 0; r < WID; ++r) {
        const float fr = (float)r;
        const float ix = fmaf(fr, s,  ix0);
        const float iy = fmaf(fr, co, iy0);

        const float fx0 = floorf(ix);
        const float fy0 = floorf(iy);
        const float tx = ix - fx0;          // exact
        const float ty = iy - fy0;          // exact

        const int x0 = (int)fx0;
        const int y0 = (int)fy0;

        const bool vx0 = (unsigned)x0       < (unsigned)WID;
        const bool vx1 = (unsigned)(x0 + 1) < (unsigned)WID;
        const bool vy0 = (unsigned)y0       < (unsigned)WID;
        const bool vy1 = (unsigned)(y0 + 1) < (unsigned)WID;

        const int base = y0 * WID + x0;

        float a0 = 0.f, b0 = 0.f, c0 = 0.f, d0 = 0.f;
        float a1 = 0.f, b1 = 0.f, c1 = 0.f, d1 = 0.f;

        if (vy0 & vx0) { a0 = __ldg(img0 + base);           a1 = __ldg(img1 + base); }
        if (vy0 & vx1) { b0 = __ldg(img0 + base + 1);       b1 = __ldg(img1 + base + 1); }
        if (vy1 & vx0) { c0 = __ldg(img0 + base + WID);     c1 = __ldg(img1 + base + WID); }
        if (vy1 & vx1) { d0 = __ldg(img0 + base + WID + 1); d1 = __ldg(img1 + base + WID + 1); }

        // bilinear lerp (== wa/wb/wc/wd formulation, within fp rounding)
        const float top0 = fmaf(tx, b0 - a0, a0);
        const float bot0 = fmaf(tx, d0 - c0, c0);
        const float top1 = fmaf(tx, b1 - a1, a1);
        const float bot1 = fmaf(tx, d1 - c1, c1);

        sum0 += fmaf(ty, bot0 - top0, top0);
        sum1 += fmaf(ty, bot1 - top1, top1);
    }

    // out[n][c][t], n-stride = 512*180, c-stride = 180
    const float scale = 1.0f / (float)WID;
    out[(size_t)c * NT + t]                 = sum0 * scale;
    out[(size_t)(WID + c) * NT + t]         = sum1 * scale;
}

extern "C" void kernel_launch(void* const* d_in, const int* in_sizes, int n_in,
                              void* d_out, int out_size)
{
    const float* x = (const float*)d_in[0];   // [2,1,512,512] fp32
    float* out = (float*)d_out;               // [2,1,512,180] fp32

    dim3 grid(2, NT);
    dim3 block(256);
    radon_kernel<<<grid, block>>>(x, out);
}

// round 5
// speedup vs baseline: 1.6514x; 1.6514x over previous
#include <cuda_runtime.h>

#define WID 512
#define NT  180
#define SEG 8
#define RPS (WID / SEG)   // 64 rows per segment

// scratch partial sums: [SEG][2][512 cols][180 thetas]
__device__ float g_scratch[SEG * 2 * WID * NT];

// grid: (2, NT, SEG) — x: column half, y: theta, z: r-segment
// block: 256 threads, one per output column c; each thread handles BOTH batches.
__global__ __launch_bounds__(256) void radon_part_kernel(
    const float* __restrict__ img)   // [2, 512, 512]
{
    const int t   = blockIdx.y;
    const int seg = blockIdx.z;
    const int c   = blockIdx.x * 256 + threadIdx.x;

    const float th = (float)t * 0.017453292519943295f;
    float s, co;
    sincosf(th, &s, &co);

    const float u = (float)c - 255.5f;
    const float ix0 = fmaf(co, u, fmaf(s, -255.5f, 255.5f));
    const float iy0 = fmaf(-s, u, fmaf(co, -255.5f, 255.5f));

    const float* __restrict__ img0 = img;
    const float* __restrict__ img1 = img + WID * WID;

    float sum0 = 0.0f, sum1 = 0.0f;

    const int rbeg = seg * RPS;

#pragma unroll 8
    for (int i = 0; i < RPS; ++i) {
        const float fr = (float)(rbeg + i);
        const float ix = fmaf(fr, s,  ix0);
        const float iy = fmaf(fr, co, iy0);

        const float fx0 = floorf(ix);
        const float fy0 = floorf(iy);
        const float tx = ix - fx0;
        const float ty = iy - fy0;

        const int x0 = (int)fx0;
        const int y0 = (int)fy0;

        const bool vx0 = (unsigned)x0       < (unsigned)WID;
        const bool vx1 = (unsigned)(x0 + 1) < (unsigned)WID;
        const bool vy0 = (unsigned)y0       < (unsigned)WID;
        const bool vy1 = (unsigned)(y0 + 1) < (unsigned)WID;

        const int base = y0 * WID + x0;

        float a0 = 0.f, b0 = 0.f, c0 = 0.f, d0 = 0.f;
        float a1 = 0.f, b1 = 0.f, c1 = 0.f, d1 = 0.f;

        if (vy0 & vx0) { a0 = __ldg(img0 + base);           a1 = __ldg(img1 + base); }
        if (vy0 & vx1) { b0 = __ldg(img0 + base + 1);       b1 = __ldg(img1 + base + 1); }
        if (vy1 & vx0) { c0 = __ldg(img0 + base + WID);     c1 = __ldg(img1 + base + WID); }
        if (vy1 & vx1) { d0 = __ldg(img0 + base + WID + 1); d1 = __ldg(img1 + base + WID + 1); }

        const float top0 = fmaf(tx, b0 - a0, a0);
        const float bot0 = fmaf(tx, d0 - c0, c0);
        const float top1 = fmaf(tx, b1 - a1, a1);
        const float bot1 = fmaf(tx, d1 - c1, c1);

        sum0 += fmaf(ty, bot0 - top0, top0);
        sum1 += fmaf(ty, bot1 - top1, top1);
    }

    g_scratch[((seg * 2 + 0) * WID + c) * NT + t] = sum0;
    g_scratch[((seg * 2 + 1) * WID + c) * NT + t] = sum1;
}

// out[n][c][t] = (1/512) * sum_seg scratch[seg][n][c][t]
__global__ __launch_bounds__(256) void radon_reduce_kernel(
    float* __restrict__ out)         // [2, 512, 180] = 184320 elems
{
    const int i = blockIdx.x * 256 + threadIdx.x;   // 0 .. 2*512*180-1
    const int n   = i / (WID * NT);
    const int rem = i - n * (WID * NT);             // = c*NT + t

    float acc = 0.0f;
#pragma unroll
    for (int seg = 0; seg < SEG; ++seg)
        acc += g_scratch[(seg * 2 + n) * (WID * NT) + rem];

    out[i] = acc * (1.0f / (float)WID);
}

extern "C" void kernel_launch(void* const* d_in, const int* in_sizes, int n_in,
                              void* d_out, int out_size)
{
    const float* x = (const float*)d_in[0];   // [2,1,512,512] fp32
    float* out = (float*)d_out;               // [2,1,512,180] fp32

    dim3 grid(2, NT, SEG);
    radon_part_kernel<<<grid, 256>>>(x);

    radon_reduce_kernel<<<(2 * WID * NT) / 256, 256>>>(out);
}

// round 7
// speedup vs baseline: 3.0196x; 1.8285x over previous
#include <cuda_runtime.h>

#define WID 512
#define NT  180
#define SEG 8
#define RPS (WID / SEG)   // 64 rows per segment

// transposed copy of both images: imgT[n][x][y] = img[n][y][x]
__device__ float g_imgT[2 * WID * WID];
// scratch partial sums: [SEG][2][512 cols][180 thetas]
__device__ float g_scratch[SEG * 2 * WID * NT];

// ── transpose prepass ── grid (16,16,2), block (32,8)
__global__ __launch_bounds__(256) void transpose_kernel(const float* __restrict__ img)
{
    __shared__ float tile[32][33];
    const int n = blockIdx.z;
    const float* __restrict__ src = img + n * WID * WID;
    float* __restrict__ dst = g_imgT + n * WID * WID;

    int x = blockIdx.x * 32 + threadIdx.x;
    int y = blockIdx.y * 32 + threadIdx.y;
#pragma unroll
    for (int j = 0; j < 32; j += 8)
        tile[threadIdx.y + j][threadIdx.x] = src[(y + j) * WID + x];
    __syncthreads();

    x = blockIdx.y * 32 + threadIdx.x;
    y = blockIdx.x * 32 + threadIdx.y;
#pragma unroll
    for (int j = 0; j < 32; j += 8)
        dst[(y + j) * WID + x] = tile[threadIdx.x][threadIdx.y + j];
}

// ── main kernel ── grid (2, NT, SEG), block 256; each thread: one column c, both batches.
__global__ __launch_bounds__(256) void radon_part_kernel(
    const float* __restrict__ img)   // [2, 512, 512]
{
    const int t   = blockIdx.y;
    const int seg = blockIdx.z;
    const int c   = blockIdx.x * 256 + threadIdx.x;

    const float th = (float)t * 0.017453292519943295f;
    float s, co;
    sincosf(th, &s, &co);

    const float u = (float)c - 255.5f;
    // ix(r) = co*u + s*r + Kx ; iy(r) = -s*u + co*r + Ky
    const float ix0 = fmaf(co, u, fmaf(s, -255.5f, 255.5f));
    const float iy0 = fmaf(-s, u, fmaf(co, -255.5f, 255.5f));

    // steep angles: sample the transposed image with swapped coords so that
    // warp-adjacent lanes read memory-adjacent addresses.
    const bool steep = fabsf(s) > fabsf(co);
    float x0c, y0c, stepx, stepy;
    const float* __restrict__ p0;
    if (!steep) { x0c = ix0; y0c = iy0; stepx = s;  stepy = co; p0 = img; }
    else        { x0c = iy0; y0c = ix0; stepx = co; stepy = s;  p0 = g_imgT; }
    const float* __restrict__ p1 = p0 + WID * WID;

    // clip r to where the sample can contribute: coord in (-1, 512) on both axes.
    float lo = 0.0f, hi = (float)WID;
    {
        if (fabsf(stepx) < 1e-6f) {
            if (x0c <= -1.0f || x0c >= (float)WID) { lo = 1.0f; hi = 0.0f; }
        } else {
            const float a = (-1.0f - x0c) / stepx;
            const float b = ((float)WID - x0c) / stepx;
            lo = fmaxf(lo, fminf(a, b));
            hi = fminf(hi, fmaxf(a, b));
        }
        if (fabsf(stepy) < 1e-6f) {
            if (y0c <= -1.0f || y0c >= (float)WID) { lo = 1.0f; hi = 0.0f; }
        } else {
            const float a = (-1.0f - y0c) / stepy;
            const float b = ((float)WID - y0c) / stepy;
            lo = fmaxf(lo, fminf(a, b));
            hi = fminf(hi, fmaxf(a, b));
        }
    }
    const int rbeg = seg * RPS;
    int r0 = rbeg, r1 = rbeg + RPS;
    // expand by 1 each side; in-loop predicates keep correctness regardless.
    if (lo > (float)r0 + 1.0f) r0 = (int)floorf(lo) - 1;
    if (hi < (float)r1 - 1.0f) r1 = (int)ceilf(hi) + 1;
    if (r1 > rbeg + RPS) r1 = rbeg + RPS;
    if (r0 < rbeg) r0 = rbeg;

    float sum0 = 0.0f, sum1 = 0.0f;

#pragma unroll 4
    for (int r = r0; r < r1; ++r) {
        const float fr = (float)r;
        const float xx = fmaf(fr, stepx, x0c);
        const float yy = fmaf(fr, stepy, y0c);

        const float fx0 = floorf(xx);
        const float fy0 = floorf(yy);
        const float tx = xx - fx0;
        const float ty = yy - fy0;

        const int x0 = (int)fx0;
        const int y0 = (int)fy0;

        const bool vx0 = (unsigned)x0       < (unsigned)WID;
        const bool vx1 = (unsigned)(x0 + 1) < (unsigned)WID;
        const bool vy0 = (unsigned)y0       < (unsigned)WID;
        const bool vy1 = (unsigned)(y0 + 1) < (unsigned)WID;

        const int base = y0 * WID + x0;

        float a0 = 0.f, b0 = 0.f, c0 = 0.f, d0 = 0.f;
        float a1 = 0.f, b1 = 0.f, c1 = 0.f, d1 = 0.f;

        if (vy0 & vx0) { a0 = __ldg(p0 + base);           a1 = __ldg(p1 + base); }
        if (vy0 & vx1) { b0 = __ldg(p0 + base + 1);       b1 = __ldg(p1 + base + 1); }
        if (vy1 & vx0) { c0 = __ldg(p0 + base + WID);     c1 = __ldg(p1 + base + WID); }
        if (vy1 & vx1) { d0 = __ldg(p0 + base + WID + 1); d1 = __ldg(p1 + base + WID + 1); }

        const float top0 = fmaf(tx, b0 - a0, a0);
        const float bot0 = fmaf(tx, d0 - c0, c0);
        const float top1 = fmaf(tx, b1 - a1, a1);
        const float bot1 = fmaf(tx, d1 - c1, c1);

        sum0 += fmaf(ty, bot0 - top0, top0);
        sum1 += fmaf(ty, bot1 - top1, top1);
    }

    g_scratch[((seg * 2 + 0) * WID + c) * NT + t] = sum0;
    g_scratch[((seg * 2 + 1) * WID + c) * NT + t] = sum1;
}

// out[n][c][t] = (1/512) * sum_seg scratch[seg][n][c][t]
__global__ __launch_bounds__(256) void radon_reduce_kernel(
    float* __restrict__ out)         // [2, 512, 180] = 184320 elems
{
    const int i = blockIdx.x * 256 + threadIdx.x;
    const int n   = i / (WID * NT);
    const int rem = i - n * (WID * NT);

    float acc = 0.0f;
#pragma unroll
    for (int seg = 0; seg < SEG; ++seg)
        acc += g_scratch[(seg * 2 + n) * (WID * NT) + rem];

    out[i] = acc * (1.0f / (float)WID);
}

extern "C" void kernel_launch(void* const* d_in, const int* in_sizes, int n_in,
                              void* d_out, int out_size)
{
    const float* x = (const float*)d_in[0];   // [2,1,512,512] fp32
    float* out = (float*)d_out;               // [2,1,512,180] fp32

    transpose_kernel<<<dim3(16, 16, 2), dim3(32, 8)>>>(x);
    radon_part_kernel<<<dim3(2, NT, SEG), 256>>>(x);
    radon_reduce_kernel<<<(2 * WID * NT) / 256, 256>>>(out);
}

// round 8
// speedup vs baseline: 4.7936x; 1.5875x over previous
#include <cuda_runtime.h>

#define WID 512
#define NT  180
#define SEG 8
#define RPS (WID / SEG)   // 64 rows per segment

// interleaved pair images: pairN[y*512+x] = (img0[y][x], img1[y][x]); pairT = transposed
__device__ float2 g_pairN[WID * WID];
__device__ float2 g_pairT[WID * WID];
// scratch partial sums: [SEG][2][512 cols][180 thetas]
__device__ float g_scratch[SEG * 2 * WID * NT];

// ── pack + transpose prepass ── grid (16,16), block (32,8)
__global__ __launch_bounds__(256) void pack_kernel(const float* __restrict__ img)
{
    __shared__ float t0[32][33];
    __shared__ float t1[32][33];

    int x = blockIdx.x * 32 + threadIdx.x;
    int y = blockIdx.y * 32 + threadIdx.y;
#pragma unroll
    for (int j = 0; j < 32; j += 8) {
        const float v0 = img[(y + j) * WID + x];
        const float v1 = img[WID * WID + (y + j) * WID + x];
        g_pairN[(y + j) * WID + x] = make_float2(v0, v1);
        t0[threadIdx.y + j][threadIdx.x] = v0;
        t1[threadIdx.y + j][threadIdx.x] = v1;
    }
    __syncthreads();

    x = blockIdx.y * 32 + threadIdx.x;
    y = blockIdx.x * 32 + threadIdx.y;
#pragma unroll
    for (int j = 0; j < 32; j += 8)
        g_pairT[(y + j) * WID + x] =
            make_float2(t0[threadIdx.x][threadIdx.y + j],
                        t1[threadIdx.x][threadIdx.y + j]);
}

// ── main kernel ── grid (2, NT, SEG), block 256; each thread: one column c, both batches.
__global__ __launch_bounds__(256) void radon_part_kernel()
{
    const int t   = blockIdx.y;
    const int seg = blockIdx.z;
    const int c   = blockIdx.x * 256 + threadIdx.x;

    const float th = (float)t * 0.017453292519943295f;
    float s, co;
    sincosf(th, &s, &co);

    const float u = (float)c - 255.5f;
    // ix(r) = co*u + s*r + Kx ; iy(r) = -s*u + co*r + Ky
    const float ix0 = fmaf(co, u, fmaf(s, -255.5f, 255.5f));
    const float iy0 = fmaf(-s, u, fmaf(co, -255.5f, 255.5f));

    // steep angles: sample the transposed pair image with swapped coords so that
    // warp-adjacent lanes read memory-adjacent addresses.
    const bool steep = fabsf(s) > fabsf(co);
    float x0c, y0c, stepx, stepy;
    const float2* __restrict__ pp;
    if (!steep) { x0c = ix0; y0c = iy0; stepx = s;  stepy = co; pp = g_pairN; }
    else        { x0c = iy0; y0c = ix0; stepx = co; stepy = s;  pp = g_pairT; }

    // clip r to where the sample can contribute: coord in (-1, 512) on both axes.
    float lo = 0.0f, hi = (float)WID;
    {
        if (fabsf(stepx) < 1e-6f) {
            if (x0c <= -1.0f || x0c >= (float)WID) { lo = 1.0f; hi = 0.0f; }
        } else {
            const float a = (-1.0f - x0c) / stepx;
            const float b = ((float)WID - x0c) / stepx;
            lo = fmaxf(lo, fminf(a, b));
            hi = fminf(hi, fmaxf(a, b));
        }
        if (fabsf(stepy) < 1e-6f) {
            if (y0c <= -1.0f || y0c >= (float)WID) { lo = 1.0f; hi = 0.0f; }
        } else {
            const float a = (-1.0f - y0c) / stepy;
            const float b = ((float)WID - y0c) / stepy;
            lo = fmaxf(lo, fminf(a, b));
            hi = fminf(hi, fmaxf(a, b));
        }
    }
    const int rbeg = seg * RPS;
    int r0 = rbeg, r1 = rbeg + RPS;
    // expand by 1 each side; in-loop predicates keep correctness regardless.
    if (lo > (float)r0 + 1.0f) r0 = (int)floorf(lo) - 1;
    if (hi < (float)r1 - 1.0f) r1 = (int)ceilf(hi) + 1;
    if (r1 > rbeg + RPS) r1 = rbeg + RPS;
    if (r0 < rbeg) r0 = rbeg;

    float sum0 = 0.0f, sum1 = 0.0f;

#pragma unroll 4
    for (int r = r0; r < r1; ++r) {
        const float fr = (float)r;
        const float xx = fmaf(fr, stepx, x0c);
        const float yy = fmaf(fr, stepy, y0c);

        const float fx0 = floorf(xx);
        const float fy0 = floorf(yy);
        const float tx = xx - fx0;
        const float ty = yy - fy0;

        const int x0 = (int)fx0;
        const int y0 = (int)fy0;

        const bool vx0 = (unsigned)x0       < (unsigned)WID;
        const bool vx1 = (unsigned)(x0 + 1) < (unsigned)WID;
        const bool vy0 = (unsigned)y0       < (unsigned)WID;
        const bool vy1 = (unsigned)(y0 + 1) < (unsigned)WID;

        const int base = y0 * WID + x0;

        float2 A = make_float2(0.f, 0.f), B = make_float2(0.f, 0.f);
        float2 C = make_float2(0.f, 0.f), D = make_float2(0.f, 0.f);

        if (vy0 & vx0) A = __ldg(pp + base);
        if (vy0 & vx1) B = __ldg(pp + base + 1);
        if (vy1 & vx0) C = __ldg(pp + base + WID);
        if (vy1 & vx1) D = __ldg(pp + base + WID + 1);

        const float top0 = fmaf(tx, B.x - A.x, A.x);
        const float bot0 = fmaf(tx, D.x - C.x, C.x);
        const float top1 = fmaf(tx, B.y - A.y, A.y);
        const float bot1 = fmaf(tx, D.y - C.y, C.y);

        sum0 += fmaf(ty, bot0 - top0, top0);
        sum1 += fmaf(ty, bot1 - top1, top1);
    }

    g_scratch[((seg * 2 + 0) * WID + c) * NT + t] = sum0;
    g_scratch[((seg * 2 + 1) * WID + c) * NT + t] = sum1;
}

// out[n][c][t] = (1/512) * sum_seg scratch[seg][n][c][t]
__global__ __launch_bounds__(256) void radon_reduce_kernel(
    float* __restrict__ out)         // [2, 512, 180] = 184320 elems
{
    const int i = blockIdx.x * 256 + threadIdx.x;
    const int n   = i / (WID * NT);
    const int rem = i - n * (WID * NT);

    float acc = 0.0f;
#pragma unroll
    for (int seg = 0; seg < SEG; ++seg)
        acc += g_scratch[(seg * 2 + n) * (WID * NT) + rem];

    out[i] = acc * (1.0f / (float)WID);
}

extern "C" void kernel_launch(void* const* d_in, const int* in_sizes, int n_in,
                              void* d_out, int out_size)
{
    const float* x = (const float*)d_in[0];   // [2,1,512,512] fp32
    float* out = (float*)d_out;               // [2,1,512,180] fp32

    pack_kernel<<<dim3(16, 16), dim3(32, 8)>>>(x);
    radon_part_kernel<<<dim3(2, NT, SEG), 256>>>();
    radon_reduce_kernel<<<(2 * WID * NT) / 256, 256>>>(out);
}